// round 12
// baseline (speedup 1.0000x reference)
#include <cuda_runtime.h>
#include <cuda_fp16.h>
#include <math.h>
#include <stdint.h>

#define BB   1024
#define NSEQ 60
#define FF   1024
#define NN   120   // 2*NSEQ

// Output layout (flattened tuple, fp32):
// x(B,2,2048) o1(B,2,1024) o2 h1 h2 ATT1(B,60,1) ATT2 att11(B,60) att22 att12 att21
#define OFF_X    0ull
#define OFF_O1   4194304ull
#define OFF_O2   6291456ull
#define OFF_H1   8388608ull
#define OFF_H2   10485760ull
#define OFF_ATT1 12582912ull
#define OFF_ATT2 12644352ull
#define OFF_A11  12705792ull
#define OFF_A22  12767232ull
#define OFF_A12  12828672ull
#define OFF_A21  12890112ull

// Scratch (1-pass fp16: A = tanh(h), B = q_w, both fp16-rounded)
static __device__ __half g_thh[4096 * 1024];   // tanh(h) fp16
static __device__ __half g_qwh[1024 * 1024];   // q_w fp16
static __device__ float  g_qm[4096 * 1024];    // qm

typedef unsigned int uint32;
typedef unsigned long long ull;
#define FULLW 0xffffffffu

__device__ __forceinline__ float dot4(float4 a, float4 b) {
    return a.x * b.x + a.y * b.y + a.z * b.z + a.w * b.w;
}
__device__ __forceinline__ uint2 h4(float4 v) {
    __half2 a = __floats2half2_rn(v.x, v.y);
    __half2 b = __floats2half2_rn(v.z, v.w);
    uint2 r;
    r.x = *reinterpret_cast<uint32*>(&a);
    r.y = *reinterpret_cast<uint32*>(&b);
    return r;
}
__device__ __forceinline__ void cpa16(uint32 dst, const void* src) {
    asm volatile("cp.async.cg.shared.global [%0], [%1], 16;" :: "r"(dst), "l"(src));
}
__device__ __forceinline__ void ldsm4(uint32* r, uint32 addr) {
    asm volatile("ldmatrix.sync.aligned.m8n8.x4.shared.b16 {%0,%1,%2,%3}, [%4];"
                 : "=r"(r[0]), "=r"(r[1]), "=r"(r[2]), "=r"(r[3]) : "r"(addr));
}
__device__ __forceinline__ void mma_f16(float* c, const uint32* a, uint32 b0, uint32 b1) {
    asm volatile(
        "mma.sync.aligned.m16n8k16.row.col.f32.f16.f16.f32 "
        "{%0,%1,%2,%3}, {%4,%5,%6,%7}, {%8,%9}, {%0,%1,%2,%3};"
        : "+f"(c[0]), "+f"(c[1]), "+f"(c[2]), "+f"(c[3])
        : "r"(a[0]), "r"(a[1]), "r"(a[2]), "r"(a[3]), "r"(b0), "r"(b1));
}

// packed f32x2 helpers (FFMA2 — only reachable via explicit PTX)
__device__ __forceinline__ ull pk2(float lo, float hi) {
    ull r;
    asm("mov.b64 %0, {%1, %2};" : "=l"(r) : "f"(lo), "f"(hi));
    return r;
}
__device__ __forceinline__ void upk2(ull c, float& lo, float& hi) {
    asm("mov.b64 {%0, %1}, %2;" : "=f"(lo), "=f"(hi) : "l"(c));
}
__device__ __forceinline__ void mul2(ull& c, ull a, ull b) {
    asm("mul.rn.f32x2 %0, %1, %2;" : "=l"(c) : "l"(a), "l"(b));
}
__device__ __forceinline__ void fma2(ull& c, ull a, ull b) {
    asm("fma.rn.f32x2 %0, %1, %2, %0;" : "+l"(c) : "l"(a), "l"(b));
}

// ---------------------------------------------------------------------------
// K0: round q_w to fp16
// ---------------------------------------------------------------------------
__global__ __launch_bounds__(256) void k_split_w(const float* __restrict__ qw)
{
    int idx = blockIdx.x * 256 + threadIdx.x;
    float4 v = ((const float4*)qw)[idx];
    *(uint2*)(g_qwh + 4 * (size_t)idx) = h4(v);
}

// ---------------------------------------------------------------------------
// K1: logits = x @ fc_w.T ; argmax ; gather h ; write h + fp16(tanh(h))
// 2 rows per warp-step (16 LDG.128 in flight) for MLP.
// ---------------------------------------------------------------------------
__global__ __launch_bounds__(256) void k_select(
    const float* __restrict__ x1, const float* __restrict__ x2,
    const float* __restrict__ fc_w, float* __restrict__ out)
{
    const int b = blockIdx.x;
    const int which = blockIdx.y;
    const float* x = which ? x2 : x1;
    const float4* x4 = (const float4*)(x + (size_t)b * NSEQ * FF);

    const int tid = threadIdx.x;
    const int w = tid >> 5, lane = tid & 31;

    __shared__ float4 s_fw[512];
    __shared__ float s_log[2][64];
    __shared__ int s_idx[2];

    const float4* fw4 = (const float4*)fc_w;
    s_fw[tid] = fw4[tid];
    s_fw[tid + 256] = fw4[tid + 256];
    __syncthreads();

#pragma unroll
    for (int k = 0; k < 8; k += 2) {
        const int n1 = w + 8 * k;
        const int n2 = n1 + 8;
        const bool v1 = n1 < NSEQ, v2 = n2 < NSEQ;
        const float4* r1 = x4 + (v1 ? n1 : 0) * 256;
        const float4* r2 = x4 + (v2 ? n2 : 0) * 256;
        float a0 = 0.f, a1 = 0.f, b0 = 0.f, b1 = 0.f;
#pragma unroll
        for (int i = 0; i < 8; i++) {
            float4 u = r1[lane + 32 * i];
            float4 v = r2[lane + 32 * i];
            float4 f0 = s_fw[lane + 32 * i];
            float4 f1 = s_fw[256 + lane + 32 * i];
            a0 += dot4(u, f0); a1 += dot4(u, f1);
            b0 += dot4(v, f0); b1 += dot4(v, f1);
        }
#pragma unroll
        for (int off = 16; off; off >>= 1) {
            a0 += __shfl_down_sync(FULLW, a0, off);
            a1 += __shfl_down_sync(FULLW, a1, off);
            b0 += __shfl_down_sync(FULLW, b0, off);
            b1 += __shfl_down_sync(FULLW, b1, off);
        }
        if (lane == 0) {
            if (v1) { s_log[0][n1] = a0; s_log[1][n1] = a1; }
            if (v2) { s_log[0][n2] = b0; s_log[1][n2] = b1; }
        }
    }
    __syncthreads();

    if (tid < 2) {
        float best = s_log[tid][0];
        int bi = 0;
        for (int n = 1; n < NSEQ; n++) {
            float v = s_log[tid][n];
            if (v > best) { best = v; bi = n; }
        }
        s_idx[tid] = bi;
    }
    __syncthreads();

    const int i0 = s_idx[0], i1 = s_idx[1];
    float4* h4o = (float4*)(out + (which ? OFF_H2 : OFF_H1) + (size_t)b * 2 * FF);
    const size_t row0 = ((size_t)b * 4 + which * 2) * FF;

    float4 v = x4[i0 * 256 + tid];
    h4o[tid] = v;
    float4 t0 = make_float4(tanhf(v.x), tanhf(v.y), tanhf(v.z), tanhf(v.w));
    *(uint2*)(g_thh + row0 + 4 * tid) = h4(t0);

    v = x4[i1 * 256 + tid];
    h4o[256 + tid] = v;
    float4 t1 = make_float4(tanhf(v.x), tanhf(v.y), tanhf(v.z), tanhf(v.w));
    *(uint2*)(g_thh + row0 + FF + 4 * tid) = h4(t1);
}

// ---------------------------------------------------------------------------
// K2: qm = th @ q_w.T + q_b -- 1-pass fp16 tensor-core GEMM (unchanged, at floor)
// ---------------------------------------------------------------------------
#define QM_ROWB 48
#define QM_AH 0
#define QM_BH 6144
#define QM_STAGE_BYTES 12288
#define QM_SMEM (3 * QM_STAGE_BYTES)

__global__ __launch_bounds__(256, 2) void k_qm_mma(const float* __restrict__ qb)
{
    extern __shared__ __align__(128) unsigned char smem[];

    const int tid = threadIdx.x;
    const int lane = tid & 31;
    const int wid = tid >> 5;
    const int warp_m = wid >> 1;
    const int warp_n = wid & 1;
    const int m0 = blockIdx.y * 128;
    const int n0 = blockIdx.x * 128;

    const uint32 sbase = (uint32)__cvta_generic_to_shared(smem);

    const int lrow = tid >> 1;
    const int lch  = tid & 1;
    const uint32 ldst = lrow * QM_ROWB + lch * 16;

    const int ag = lane >> 3;
    const uint32 a_off = (warp_m * 32 + (lane & 7) + (ag & 1) * 8) * QM_ROWB + (ag >> 1) * 16;
    const uint32 b_off = (warp_n * 64 + (lane & 7) + ((lane >> 4) & 1) * 8) * QM_ROWB
                         + ((lane >> 3) & 1) * 16;

    float c[2][8][4];
#pragma unroll
    for (int mt = 0; mt < 2; mt++)
#pragma unroll
        for (int nt = 0; nt < 8; nt++)
#pragma unroll
            for (int i = 0; i < 4; i++) c[mt][nt][i] = 0.f;

#pragma unroll
    for (int s = 0; s < 2; s++) {
        const uint32 st = s * QM_STAGE_BYTES;
        const size_t ka = (size_t)(m0 + lrow) * 1024 + s * 16 + lch * 8;
        const size_t kb = (size_t)(n0 + lrow) * 1024 + s * 16 + lch * 8;
        cpa16(sbase + st + QM_AH + ldst, g_thh + ka);
        cpa16(sbase + st + QM_BH + ldst, g_qwh + kb);
        asm volatile("cp.async.commit_group;");
    }

    int cur_s = 0, nxt_s = 2;
    for (int it = 0; it < 64; it++) {
        const uint32 cur = cur_s * QM_STAGE_BYTES;
        asm volatile("cp.async.wait_group 1;");
        __syncthreads();

        if (it < 62) {
            const uint32 nxt = nxt_s * QM_STAGE_BYTES;
            const size_t ka = (size_t)(m0 + lrow) * 1024 + (it + 2) * 16 + lch * 8;
            const size_t kb = (size_t)(n0 + lrow) * 1024 + (it + 2) * 16 + lch * 8;
            cpa16(sbase + nxt + QM_AH + ldst, g_thh + ka);
            cpa16(sbase + nxt + QM_BH + ldst, g_qwh + kb);
            asm volatile("cp.async.commit_group;");
        } else {
            asm volatile("cp.async.commit_group;");
        }

        uint32 ah[2][4];
#pragma unroll
        for (int mt = 0; mt < 2; mt++)
            ldsm4(ah[mt], sbase + cur + QM_AH + a_off + mt * 16 * QM_ROWB);
#pragma unroll
        for (int p = 0; p < 4; p++) {
            uint32 bh[4];
            ldsm4(bh, sbase + cur + QM_BH + b_off + p * 16 * QM_ROWB);
#pragma unroll
            for (int mt = 0; mt < 2; mt++) {
                mma_f16(c[mt][2 * p],     ah[mt], bh[0], bh[1]);
                mma_f16(c[mt][2 * p + 1], ah[mt], bh[2], bh[3]);
            }
        }
        cur_s = (cur_s == 2) ? 0 : cur_s + 1;
        nxt_s = (nxt_s == 2) ? 0 : nxt_s + 1;
    }

#pragma unroll
    for (int mt = 0; mt < 2; mt++) {
        const int mg = m0 + warp_m * 32 + mt * 16 + (lane >> 2);
#pragma unroll
        for (int nt = 0; nt < 8; nt++) {
            const int ng = n0 + warp_n * 64 + nt * 8 + 2 * (lane & 3);
            const float b0 = __ldg(qb + ng), b1 = __ldg(qb + ng + 1);
            *(float2*)(g_qm + (size_t)mg * 1024 + ng) =
                make_float2(c[mt][nt][0] + b0, c[mt][nt][1] + b1);
            *(float2*)(g_qm + (size_t)(mg + 8) * 1024 + ng) =
                make_float2(c[mt][nt][2] + b0, c[mt][nt][3] + b1);
        }
    }
}

// ---------------------------------------------------------------------------
// K3: fused attention (R10 structure: 4-stage cp.async, 1 barrier/iter,
// 3 CTAs/SM) with packed f32x2 math for dots and o-accumulation.
// ---------------------------------------------------------------------------
#define AT_L    0
#define AT_SS   65536
#define AT_RED  67456      // 2 x 8 x 16 floats = 1024 B
#define AT_SMEM 68480

__global__ __launch_bounds__(256, 3) void k_attend(
    const float* __restrict__ x1, const float* __restrict__ x2,
    float* __restrict__ out)
{
    extern __shared__ __align__(16) unsigned char smem[];
    float4* s_L  = (float4*)(smem + AT_L);
    float (*s_s)[4] = (float (*)[4])(smem + AT_SS);
    float (*s_red)[8][16] = (float (*)[8][16])(smem + AT_RED);

    const int b = blockIdx.x;
    const int tid = threadIdx.x;
    const int w = tid >> 5, lane = tid & 31;
    const uint32 sL = (uint32)__cvta_generic_to_shared(s_L);

    const float* x1b = x1 + (size_t)b * NSEQ * FF;
    const float* x2b = x2 + (size_t)b * NSEQ * FF;
    const float4* qmg = (const float4*)(g_qm + (size_t)b * 4 * FF);

#define AT_ISSUE(bt)                                                          \
    {                                                                         \
        const int _st = (bt) & 3;                                             \
        _Pragma("unroll")                                                     \
        for (int _r = 0; _r < 4; _r++) {                                      \
            int _n = (bt) * 4 + _r;                                           \
            const float* _src = (_n < NSEQ) ? (x1b + (size_t)_n * FF)         \
                                            : (x2b + (size_t)(_n - NSEQ) * FF); \
            cpa16(sL + ((_st * 4 + _r) * 256 + tid) * 16, _src + 4 * tid);    \
        }                                                                     \
        asm volatile("cp.async.commit_group;");                               \
    }

    AT_ISSUE(0); AT_ISSUE(1); AT_ISSUE(2);

    // qm lives only in packed form (unpacked at epilogue) — register-neutral
    ull qm2[4][2];
#pragma unroll
    for (int j = 0; j < 4; j++) {
        float4 q = qmg[j * 256 + tid];
        qm2[j][0] = pk2(q.x, q.y);
        qm2[j][1] = pk2(q.z, q.w);
    }

    ull o2[4][2];
#pragma unroll
    for (int j = 0; j < 4; j++) { o2[j][0] = 0ull; o2[j][1] = 0ull; }

    float lsum = 0.f;                  // lane l<16: weight sum for (r=l>>2, j=l&3)
    const float scale = 0.03125f;

    // prologue: stage 0 ready
    asm volatile("cp.async.wait_group 2;");
    __syncthreads();

    for (int bt = 0; bt < 30; bt++) {
        const int st = bt & 3;
        const int par = bt & 1;

        ull rv2[4][2];
#pragma unroll
        for (int r = 0; r < 4; r++) {
            float4 t = s_L[(st * 4 + r) * 256 + tid];
            rv2[r][0] = pk2(t.x, t.y);
            rv2[r][1] = pk2(t.z, t.w);
        }

        if (bt + 3 < 30) { AT_ISSUE(bt + 3); }
        else { asm volatile("cp.async.commit_group;"); }

        // 16 dots via packed FMA: mul2 + fma2 + horizontal add
        float p[16];
#pragma unroll
        for (int r = 0; r < 4; r++)
#pragma unroll
            for (int j = 0; j < 4; j++) {
                ull acc;
                mul2(acc, rv2[r][0], qm2[j][0]);
                fma2(acc, rv2[r][1], qm2[j][1]);
                float lo, hi;
                upk2(acc, lo, hi);
                p[r * 4 + j] = lo + hi;
            }

#pragma unroll
        for (int v = 0; v < 16; v++) p[v] += __shfl_xor_sync(FULLW, p[v], 16);
        float q8[8];
#pragma unroll
        for (int v = 0; v < 8; v++) q8[v] = (lane & 16) ? p[v + 8] : p[v];
#pragma unroll
        for (int v = 0; v < 8; v++) q8[v] += __shfl_xor_sync(FULLW, q8[v], 8);
        float q4[4];
#pragma unroll
        for (int v = 0; v < 4; v++) q4[v] = (lane & 8) ? q8[v + 4] : q8[v];
#pragma unroll
        for (int v = 0; v < 4; v++) q4[v] += __shfl_xor_sync(FULLW, q4[v], 4);
        float q2[2];
#pragma unroll
        for (int v = 0; v < 2; v++) q2[v] = (lane & 4) ? q4[v + 2] : q4[v];
#pragma unroll
        for (int v = 0; v < 2; v++) q2[v] += __shfl_xor_sync(FULLW, q2[v], 2);
        float q1 = (lane & 2) ? q2[1] : q2[0];
        q1 += __shfl_xor_sync(FULLW, q1, 1);

        if (!(lane & 1)) s_red[par][w][lane >> 1] = q1;

        // single barrier: s_red[par] visible + stage bt+1 data arrived
        asm volatile("cp.async.wait_group 2;");
        __syncthreads();

        float v16 = 0.f;
        if (lane < 16) {
#pragma unroll
            for (int ww = 0; ww < 8; ww++) v16 += s_red[par][ww][lane];
            v16 *= scale;
        }
        if (w == 0 && lane < 16) s_s[bt * 4 + (lane >> 2)][lane & 3] = v16;

        float wexp = __expf(v16);      // lanes>=16 unused
        lsum += wexp;

        // packed o-update: o2[j] += (w,w) * rv2[r]
#pragma unroll
        for (int r = 0; r < 4; r++) {
#pragma unroll
            for (int j = 0; j < 4; j++) {
                float wv = __shfl_sync(FULLW, wexp, r * 4 + j);
                ull ww2 = pk2(wv, wv);
                fma2(o2[j][0], ww2, rv2[r][0]);
                fma2(o2[j][1], ww2, rv2[r][1]);
            }
        }
    }
    __syncthreads();   // s_s final writes visible for tail readers

    float linv[4];
#pragma unroll
    for (int j = 0; j < 4; j++) {
        float t = __shfl_sync(FULLW, lsum, j)
                + __shfl_sync(FULLW, lsum, 4 + j)
                + __shfl_sync(FULLW, lsum, 8 + j)
                + __shfl_sync(FULLW, lsum, 12 + j);
        linv[j] = 1.f / t;
    }

#pragma unroll
    for (int j = 0; j < 4; j++) {
        float qx, qy, qz, qw, ox, oy, oz, ow;
        upk2(qm2[j][0], qx, qy);
        upk2(qm2[j][1], qz, qw);
        upk2(o2[j][0], ox, oy);
        upk2(o2[j][1], oz, ow);
        float4 val;
        val.x = 0.9f * ox * linv[j] + 0.1f * qx;
        val.y = 0.9f * oy * linv[j] + 0.1f * qy;
        val.z = 0.9f * oz * linv[j] + 0.1f * qz;
        val.w = 0.9f * ow * linv[j] + 0.1f * qw;
        if (j < 2) {
            *(float4*)(out + OFF_O1 + ((size_t)b * 2 + j) * FF + 4 * tid) = val;
            *(float4*)(out + OFF_X + ((size_t)b * 2 + j) * 2048 + 4 * tid) = val;
        } else {
            *(float4*)(out + OFF_O2 + ((size_t)b * 2 + (j - 2)) * FF + 4 * tid) = val;
            *(float4*)(out + OFF_X + ((size_t)b * 2 + (j - 2)) * 2048 + 1024 + 4 * tid) = val;
        }
    }

    if (tid < NN) {
        int n = tid;
        float s0 = s_s[n][0], s1 = s_s[n][1], s2 = s_s[n][2], s3 = s_s[n][3];
        if (n < NSEQ) {
            out[OFF_ATT1 + (size_t)b * 60 + n] = __expf(s0) * linv[0];
            out[OFF_A11 + (size_t)b * 60 + n]  = __expf(s1) * linv[1];
            out[OFF_A21 + (size_t)b * 60 + n]  = __expf(s3) * linv[3];
        } else {
            int nn = n - NSEQ;
            out[OFF_ATT2 + (size_t)b * 60 + nn] = __expf(s2) * linv[2];
            out[OFF_A12 + (size_t)b * 60 + nn]  = __expf(s1) * linv[1];
            out[OFF_A22 + (size_t)b * 60 + nn]  = __expf(s3) * linv[3];
        }
    }
#undef AT_ISSUE
}

// ---------------------------------------------------------------------------
extern "C" void kernel_launch(void* const* d_in, const int* in_sizes, int n_in,
                              void* d_out, int out_size)
{
    (void)in_sizes; (void)n_in; (void)out_size;
    const float* x1   = (const float*)d_in[0];
    const float* x2   = (const float*)d_in[1];
    const float* fc_w = (const float*)d_in[2];
    // d_in[3] = fc_b (constant per class: doesn't change argmax over n)
    const float* q_w  = (const float*)d_in[4];
    const float* q_b  = (const float*)d_in[5];
    float* out = (float*)d_out;

    k_split_w<<<1024, 256>>>(q_w);

    dim3 g1(BB, 2);
    k_select<<<g1, 256>>>(x1, x2, fc_w, out);

    cudaFuncSetAttribute(k_qm_mma, cudaFuncAttributeMaxDynamicSharedMemorySize, QM_SMEM);
    dim3 g2(8, 32);   // (N/128, M/128)
    k_qm_mma<<<g2, 256, QM_SMEM>>>(q_b);

    cudaFuncSetAttribute(k_attend, cudaFuncAttributeMaxDynamicSharedMemorySize, AT_SMEM);
    k_attend<<<BB, 256, AT_SMEM>>>(x1, x2, out);
}

// round 13
// speedup vs baseline: 1.0544x; 1.0544x over previous
#include <cuda_runtime.h>
#include <cuda_fp16.h>
#include <math.h>
#include <stdint.h>

#define BB   1024
#define NSEQ 60
#define FF   1024
#define NN   120   // 2*NSEQ

// Output layout (flattened tuple, fp32):
// x(B,2,2048) o1(B,2,1024) o2 h1 h2 ATT1(B,60,1) ATT2 att11(B,60) att22 att12 att21
#define OFF_X    0ull
#define OFF_O1   4194304ull
#define OFF_O2   6291456ull
#define OFF_H1   8388608ull
#define OFF_H2   10485760ull
#define OFF_ATT1 12582912ull
#define OFF_ATT2 12644352ull
#define OFF_A11  12705792ull
#define OFF_A22  12767232ull
#define OFF_A12  12828672ull
#define OFF_A21  12890112ull

// Scratch (1-pass fp16: A = tanh(h), B = q_w, both fp16-rounded)
static __device__ __half g_thh[4096 * 1024];   // tanh(h) fp16
static __device__ __half g_qwh[1024 * 1024];   // q_w fp16
static __device__ float  g_qm[4096 * 1024];    // qm

typedef unsigned int uint32;
typedef unsigned long long ull;
#define FULLW 0xffffffffu

__device__ __forceinline__ float dot4(float4 a, float4 b) {
    return a.x * b.x + a.y * b.y + a.z * b.z + a.w * b.w;
}
__device__ __forceinline__ uint2 h4(float4 v) {
    __half2 a = __floats2half2_rn(v.x, v.y);
    __half2 b = __floats2half2_rn(v.z, v.w);
    uint2 r;
    r.x = *reinterpret_cast<uint32*>(&a);
    r.y = *reinterpret_cast<uint32*>(&b);
    return r;
}
__device__ __forceinline__ void cpa16(uint32 dst, const void* src) {
    asm volatile("cp.async.cg.shared.global [%0], [%1], 16;" :: "r"(dst), "l"(src));
}
__device__ __forceinline__ void ldsm4(uint32* r, uint32 addr) {
    asm volatile("ldmatrix.sync.aligned.m8n8.x4.shared.b16 {%0,%1,%2,%3}, [%4];"
                 : "=r"(r[0]), "=r"(r[1]), "=r"(r[2]), "=r"(r[3]) : "r"(addr));
}
__device__ __forceinline__ void mma_f16(float* c, const uint32* a, uint32 b0, uint32 b1) {
    asm volatile(
        "mma.sync.aligned.m16n8k16.row.col.f32.f16.f16.f32 "
        "{%0,%1,%2,%3}, {%4,%5,%6,%7}, {%8,%9}, {%0,%1,%2,%3};"
        : "+f"(c[0]), "+f"(c[1]), "+f"(c[2]), "+f"(c[3])
        : "r"(a[0]), "r"(a[1]), "r"(a[2]), "r"(a[3]), "r"(b0), "r"(b1));
}

// packed f32x2 helpers (FFMA2 — only reachable via explicit PTX)
__device__ __forceinline__ ull pk2(float lo, float hi) {
    ull r;
    asm("mov.b64 %0, {%1, %2};" : "=l"(r) : "f"(lo), "f"(hi));
    return r;
}
__device__ __forceinline__ void upk2(ull c, float& lo, float& hi) {
    asm("mov.b64 {%0, %1}, %2;" : "=f"(lo), "=f"(hi) : "l"(c));
}
__device__ __forceinline__ void mul2(ull& c, ull a, ull b) {
    asm("mul.rn.f32x2 %0, %1, %2;" : "=l"(c) : "l"(a), "l"(b));
}
__device__ __forceinline__ void fma2(ull& c, ull a, ull b) {
    asm("fma.rn.f32x2 %0, %1, %2, %0;" : "+l"(c) : "l"(a), "l"(b));
}

// ---------------------------------------------------------------------------
// K0: round q_w to fp16
// ---------------------------------------------------------------------------
__global__ __launch_bounds__(256) void k_split_w(const float* __restrict__ qw)
{
    int idx = blockIdx.x * 256 + threadIdx.x;
    float4 v = ((const float4*)qw)[idx];
    *(uint2*)(g_qwh + 4 * (size_t)idx) = h4(v);
}

// ---------------------------------------------------------------------------
// K1: logits = x @ fc_w.T ; argmax ; gather h ; write h + fp16(tanh(h))
// (R10-proven single-row loop)
// ---------------------------------------------------------------------------
__global__ __launch_bounds__(256) void k_select(
    const float* __restrict__ x1, const float* __restrict__ x2,
    const float* __restrict__ fc_w, float* __restrict__ out)
{
    const int b = blockIdx.x;
    const int which = blockIdx.y;
    const float* x = which ? x2 : x1;
    const float4* x4 = (const float4*)(x + (size_t)b * NSEQ * FF);

    const int tid = threadIdx.x;
    const int w = tid >> 5, lane = tid & 31;

    __shared__ float4 s_fw[512];
    __shared__ float s_log[2][64];
    __shared__ int s_idx[2];

    const float4* fw4 = (const float4*)fc_w;
    s_fw[tid] = fw4[tid];
    s_fw[tid + 256] = fw4[tid + 256];
    __syncthreads();

    for (int n = w; n < NSEQ; n += 8) {
        const float4* row = x4 + n * 256;
        float p0 = 0.f, p1 = 0.f;
#pragma unroll
        for (int i = 0; i < 8; i++) {
            float4 v = row[lane + 32 * i];
            p0 += dot4(v, s_fw[lane + 32 * i]);
            p1 += dot4(v, s_fw[256 + lane + 32 * i]);
        }
#pragma unroll
        for (int off = 16; off; off >>= 1) {
            p0 += __shfl_down_sync(FULLW, p0, off);
            p1 += __shfl_down_sync(FULLW, p1, off);
        }
        if (lane == 0) { s_log[0][n] = p0; s_log[1][n] = p1; }
    }
    __syncthreads();

    if (tid < 2) {
        float best = s_log[tid][0];
        int bi = 0;
        for (int n = 1; n < NSEQ; n++) {
            float v = s_log[tid][n];
            if (v > best) { best = v; bi = n; }
        }
        s_idx[tid] = bi;
    }
    __syncthreads();

    const int i0 = s_idx[0], i1 = s_idx[1];
    float4* h4o = (float4*)(out + (which ? OFF_H2 : OFF_H1) + (size_t)b * 2 * FF);
    const size_t row0 = ((size_t)b * 4 + which * 2) * FF;

    float4 v = x4[i0 * 256 + tid];
    h4o[tid] = v;
    float4 t0 = make_float4(tanhf(v.x), tanhf(v.y), tanhf(v.z), tanhf(v.w));
    *(uint2*)(g_thh + row0 + 4 * tid) = h4(t0);

    v = x4[i1 * 256 + tid];
    h4o[256 + tid] = v;
    float4 t1 = make_float4(tanhf(v.x), tanhf(v.y), tanhf(v.z), tanhf(v.w));
    *(uint2*)(g_thh + row0 + FF + 4 * tid) = h4(t1);
}

// ---------------------------------------------------------------------------
// K2: qm = th @ q_w.T + q_b -- 1-pass fp16 tensor-core GEMM (at HMMA floor)
// ---------------------------------------------------------------------------
#define QM_ROWB 48
#define QM_AH 0
#define QM_BH 6144
#define QM_STAGE_BYTES 12288
#define QM_SMEM (3 * QM_STAGE_BYTES)

__global__ __launch_bounds__(256, 2) void k_qm_mma(const float* __restrict__ qb)
{
    extern __shared__ __align__(128) unsigned char smem[];

    const int tid = threadIdx.x;
    const int lane = tid & 31;
    const int wid = tid >> 5;
    const int warp_m = wid >> 1;
    const int warp_n = wid & 1;
    const int m0 = blockIdx.y * 128;
    const int n0 = blockIdx.x * 128;

    const uint32 sbase = (uint32)__cvta_generic_to_shared(smem);

    const int lrow = tid >> 1;
    const int lch  = tid & 1;
    const uint32 ldst = lrow * QM_ROWB + lch * 16;

    const int ag = lane >> 3;
    const uint32 a_off = (warp_m * 32 + (lane & 7) + (ag & 1) * 8) * QM_ROWB + (ag >> 1) * 16;
    const uint32 b_off = (warp_n * 64 + (lane & 7) + ((lane >> 4) & 1) * 8) * QM_ROWB
                         + ((lane >> 3) & 1) * 16;

    float c[2][8][4];
#pragma unroll
    for (int mt = 0; mt < 2; mt++)
#pragma unroll
        for (int nt = 0; nt < 8; nt++)
#pragma unroll
            for (int i = 0; i < 4; i++) c[mt][nt][i] = 0.f;

#pragma unroll
    for (int s = 0; s < 2; s++) {
        const uint32 st = s * QM_STAGE_BYTES;
        const size_t ka = (size_t)(m0 + lrow) * 1024 + s * 16 + lch * 8;
        const size_t kb = (size_t)(n0 + lrow) * 1024 + s * 16 + lch * 8;
        cpa16(sbase + st + QM_AH + ldst, g_thh + ka);
        cpa16(sbase + st + QM_BH + ldst, g_qwh + kb);
        asm volatile("cp.async.commit_group;");
    }

    int cur_s = 0, nxt_s = 2;
    for (int it = 0; it < 64; it++) {
        const uint32 cur = cur_s * QM_STAGE_BYTES;
        asm volatile("cp.async.wait_group 1;");
        __syncthreads();

        if (it < 62) {
            const uint32 nxt = nxt_s * QM_STAGE_BYTES;
            const size_t ka = (size_t)(m0 + lrow) * 1024 + (it + 2) * 16 + lch * 8;
            const size_t kb = (size_t)(n0 + lrow) * 1024 + (it + 2) * 16 + lch * 8;
            cpa16(sbase + nxt + QM_AH + ldst, g_thh + ka);
            cpa16(sbase + nxt + QM_BH + ldst, g_qwh + kb);
            asm volatile("cp.async.commit_group;");
        } else {
            asm volatile("cp.async.commit_group;");
        }

        uint32 ah[2][4];
#pragma unroll
        for (int mt = 0; mt < 2; mt++)
            ldsm4(ah[mt], sbase + cur + QM_AH + a_off + mt * 16 * QM_ROWB);
#pragma unroll
        for (int p = 0; p < 4; p++) {
            uint32 bh[4];
            ldsm4(bh, sbase + cur + QM_BH + b_off + p * 16 * QM_ROWB);
#pragma unroll
            for (int mt = 0; mt < 2; mt++) {
                mma_f16(c[mt][2 * p],     ah[mt], bh[0], bh[1]);
                mma_f16(c[mt][2 * p + 1], ah[mt], bh[2], bh[3]);
            }
        }
        cur_s = (cur_s == 2) ? 0 : cur_s + 1;
        nxt_s = (nxt_s == 2) ? 0 : nxt_s + 1;
    }

#pragma unroll
    for (int mt = 0; mt < 2; mt++) {
        const int mg = m0 + warp_m * 32 + mt * 16 + (lane >> 2);
#pragma unroll
        for (int nt = 0; nt < 8; nt++) {
            const int ng = n0 + warp_n * 64 + nt * 8 + 2 * (lane & 3);
            const float b0 = __ldg(qb + ng), b1 = __ldg(qb + ng + 1);
            *(float2*)(g_qm + (size_t)mg * 1024 + ng) =
                make_float2(c[mt][nt][0] + b0, c[mt][nt][1] + b1);
            *(float2*)(g_qm + (size_t)(mg + 8) * 1024 + ng) =
                make_float2(c[mt][nt][2] + b0, c[mt][nt][3] + b1);
        }
    }
}

// ---------------------------------------------------------------------------
// K3: fused attention (4-stage cp.async, 1 barrier/iter, 3 CTAs/SM) with
// packed f32x2 math for dots and o-accumulation. (R12-measured 98.6us)
// ---------------------------------------------------------------------------
#define AT_L    0
#define AT_SS   65536
#define AT_RED  67456      // 2 x 8 x 16 floats = 1024 B
#define AT_SMEM 68480

__global__ __launch_bounds__(256, 3) void k_attend(
    const float* __restrict__ x1, const float* __restrict__ x2,
    float* __restrict__ out)
{
    extern __shared__ __align__(16) unsigned char smem[];
    float4* s_L  = (float4*)(smem + AT_L);
    float (*s_s)[4] = (float (*)[4])(smem + AT_SS);
    float (*s_red)[8][16] = (float (*)[8][16])(smem + AT_RED);

    const int b = blockIdx.x;
    const int tid = threadIdx.x;
    const int w = tid >> 5, lane = tid & 31;
    const uint32 sL = (uint32)__cvta_generic_to_shared(s_L);

    const float* x1b = x1 + (size_t)b * NSEQ * FF;
    const float* x2b = x2 + (size_t)b * NSEQ * FF;
    const float4* qmg = (const float4*)(g_qm + (size_t)b * 4 * FF);

#define AT_ISSUE(bt)                                                          \
    {                                                                         \
        const int _st = (bt) & 3;                                             \
        _Pragma("unroll")                                                     \
        for (int _r = 0; _r < 4; _r++) {                                      \
            int _n = (bt) * 4 + _r;                                           \
            const float* _src = (_n < NSEQ) ? (x1b + (size_t)_n * FF)         \
                                            : (x2b + (size_t)(_n - NSEQ) * FF); \
            cpa16(sL + ((_st * 4 + _r) * 256 + tid) * 16, _src + 4 * tid);    \
        }                                                                     \
        asm volatile("cp.async.commit_group;");                               \
    }

    AT_ISSUE(0); AT_ISSUE(1); AT_ISSUE(2);

    // qm lives only in packed form (unpacked at epilogue) — register-neutral
    ull qm2[4][2];
#pragma unroll
    for (int j = 0; j < 4; j++) {
        float4 q = qmg[j * 256 + tid];
        qm2[j][0] = pk2(q.x, q.y);
        qm2[j][1] = pk2(q.z, q.w);
    }

    ull o2[4][2];
#pragma unroll
    for (int j = 0; j < 4; j++) { o2[j][0] = 0ull; o2[j][1] = 0ull; }

    float lsum = 0.f;                  // lane l<16: weight sum for (r=l>>2, j=l&3)
    const float scale = 0.03125f;

    // prologue: stage 0 ready
    asm volatile("cp.async.wait_group 2;");
    __syncthreads();

    for (int bt = 0; bt < 30; bt++) {
        const int st = bt & 3;
        const int par = bt & 1;

        ull rv2[4][2];
#pragma unroll
        for (int r = 0; r < 4; r++) {
            float4 t = s_L[(st * 4 + r) * 256 + tid];
            rv2[r][0] = pk2(t.x, t.y);
            rv2[r][1] = pk2(t.z, t.w);
        }

        if (bt + 3 < 30) { AT_ISSUE(bt + 3); }
        else { asm volatile("cp.async.commit_group;"); }

        // 16 dots via packed FMA: mul2 + fma2 + horizontal add
        float p[16];
#pragma unroll
        for (int r = 0; r < 4; r++)
#pragma unroll
            for (int j = 0; j < 4; j++) {
                ull acc;
                mul2(acc, rv2[r][0], qm2[j][0]);
                fma2(acc, rv2[r][1], qm2[j][1]);
                float lo, hi;
                upk2(acc, lo, hi);
                p[r * 4 + j] = lo + hi;
            }

#pragma unroll
        for (int v = 0; v < 16; v++) p[v] += __shfl_xor_sync(FULLW, p[v], 16);
        float q8[8];
#pragma unroll
        for (int v = 0; v < 8; v++) q8[v] = (lane & 16) ? p[v + 8] : p[v];
#pragma unroll
        for (int v = 0; v < 8; v++) q8[v] += __shfl_xor_sync(FULLW, q8[v], 8);
        float q4[4];
#pragma unroll
        for (int v = 0; v < 4; v++) q4[v] = (lane & 8) ? q8[v + 4] : q8[v];
#pragma unroll
        for (int v = 0; v < 4; v++) q4[v] += __shfl_xor_sync(FULLW, q4[v], 4);
        float q2[2];
#pragma unroll
        for (int v = 0; v < 2; v++) q2[v] = (lane & 4) ? q4[v + 2] : q4[v];
#pragma unroll
        for (int v = 0; v < 2; v++) q2[v] += __shfl_xor_sync(FULLW, q2[v], 2);
        float q1 = (lane & 2) ? q2[1] : q2[0];
        q1 += __shfl_xor_sync(FULLW, q1, 1);

        if (!(lane & 1)) s_red[par][w][lane >> 1] = q1;

        // single barrier: s_red[par] visible + stage bt+1 data arrived
        asm volatile("cp.async.wait_group 2;");
        __syncthreads();

        float v16 = 0.f;
        if (lane < 16) {
#pragma unroll
            for (int ww = 0; ww < 8; ww++) v16 += s_red[par][ww][lane];
            v16 *= scale;
        }
        if (w == 0 && lane < 16) s_s[bt * 4 + (lane >> 2)][lane & 3] = v16;

        float wexp = __expf(v16);      // lanes>=16 unused
        lsum += wexp;

        // packed o-update: o2[j] += (w,w) * rv2[r]
#pragma unroll
        for (int r = 0; r < 4; r++) {
#pragma unroll
            for (int j = 0; j < 4; j++) {
                float wv = __shfl_sync(FULLW, wexp, r * 4 + j);
                ull ww2 = pk2(wv, wv);
                fma2(o2[j][0], ww2, rv2[r][0]);
                fma2(o2[j][1], ww2, rv2[r][1]);
            }
        }
    }
    __syncthreads();   // s_s final writes visible for tail readers

    float linv[4];
#pragma unroll
    for (int j = 0; j < 4; j++) {
        float t = __shfl_sync(FULLW, lsum, j)
                + __shfl_sync(FULLW, lsum, 4 + j)
                + __shfl_sync(FULLW, lsum, 8 + j)
                + __shfl_sync(FULLW, lsum, 12 + j);
        linv[j] = 1.f / t;
    }

#pragma unroll
    for (int j = 0; j < 4; j++) {
        float qx, qy, qz, qw, ox, oy, oz, ow;
        upk2(qm2[j][0], qx, qy);
        upk2(qm2[j][1], qz, qw);
        upk2(o2[j][0], ox, oy);
        upk2(o2[j][1], oz, ow);
        float4 val;
        val.x = 0.9f * ox * linv[j] + 0.1f * qx;
        val.y = 0.9f * oy * linv[j] + 0.1f * qy;
        val.z = 0.9f * oz * linv[j] + 0.1f * qz;
        val.w = 0.9f * ow * linv[j] + 0.1f * qw;
        if (j < 2) {
            *(float4*)(out + OFF_O1 + ((size_t)b * 2 + j) * FF + 4 * tid) = val;
            *(float4*)(out + OFF_X + ((size_t)b * 2 + j) * 2048 + 4 * tid) = val;
        } else {
            *(float4*)(out + OFF_O2 + ((size_t)b * 2 + (j - 2)) * FF + 4 * tid) = val;
            *(float4*)(out + OFF_X + ((size_t)b * 2 + (j - 2)) * 2048 + 1024 + 4 * tid) = val;
        }
    }

    if (tid < NN) {
        int n = tid;
        float s0 = s_s[n][0], s1 = s_s[n][1], s2 = s_s[n][2], s3 = s_s[n][3];
        if (n < NSEQ) {
            out[OFF_ATT1 + (size_t)b * 60 + n] = __expf(s0) * linv[0];
            out[OFF_A11 + (size_t)b * 60 + n]  = __expf(s1) * linv[1];
            out[OFF_A21 + (size_t)b * 60 + n]  = __expf(s3) * linv[3];
        } else {
            int nn = n - NSEQ;
            out[OFF_ATT2 + (size_t)b * 60 + nn] = __expf(s2) * linv[2];
            out[OFF_A12 + (size_t)b * 60 + nn]  = __expf(s1) * linv[1];
            out[OFF_A22 + (size_t)b * 60 + nn]  = __expf(s3) * linv[3];
        }
    }
#undef AT_ISSUE
}

// ---------------------------------------------------------------------------
extern "C" void kernel_launch(void* const* d_in, const int* in_sizes, int n_in,
                              void* d_out, int out_size)
{
    (void)in_sizes; (void)n_in; (void)out_size;
    const float* x1   = (const float*)d_in[0];
    const float* x2   = (const float*)d_in[1];
    const float* fc_w = (const float*)d_in[2];
    // d_in[3] = fc_b (constant per class: doesn't change argmax over n)
    const float* q_w  = (const float*)d_in[4];
    const float* q_b  = (const float*)d_in[5];
    float* out = (float*)d_out;

    k_split_w<<<1024, 256>>>(q_w);

    dim3 g1(BB, 2);
    k_select<<<g1, 256>>>(x1, x2, fc_w, out);

    cudaFuncSetAttribute(k_qm_mma, cudaFuncAttributeMaxDynamicSharedMemorySize, QM_SMEM);
    dim3 g2(8, 32);   // (N/128, M/128)
    k_qm_mma<<<g2, 256, QM_SMEM>>>(q_b);

    cudaFuncSetAttribute(k_attend, cudaFuncAttributeMaxDynamicSharedMemorySize, AT_SMEM);
    k_attend<<<BB, 256, AT_SMEM>>>(x1, x2, out);
}